// round 6
// baseline (speedup 1.0000x reference)
#include <cuda_runtime.h>
#include <math.h>
#include <stdint.h>

#define SEQ 4096
#define DIN 2048
#define DOUT 2048

// Scratch (static device globals -- no allocation at runtime)
__device__ float g_Q[SEQ * DOUT];
__device__ float g_K[SEQ * DOUT];
__device__ float g_V[SEQ * DOUT];
__device__ float g_P[(size_t)SEQ * SEQ];

__device__ __forceinline__ uint32_t rotl32(uint32_t x, int d) {
    return __funnelshift_l(x, x, d);
}

// JAX threefry2x32, PARTITIONABLE scheme (jax_threefry_partitionable=True,
// default since jax 0.4.30). key = jax.random.key(42) -> (k0=0, k1=42).
// For flat element index idx: 64-bit counter c = idx, threefry input words
// (x0, x1) = (hi32(c), lo32(c)) = (0, idx) since idx < 2^32. 32-bit output
// folds both output words: bits = o0 ^ o1.
__device__ __forceinline__ uint32_t threefry_bits(uint32_t idx) {
    const uint32_t k0 = 0u, k1 = 42u;
    const uint32_t k2 = 0x1BD11BDAu ^ k0 ^ k1;
    uint32_t x0 = 0u + k0, x1 = idx + k1;
#define TF_R(r) { x0 += x1; x1 = rotl32(x1, (r)); x1 ^= x0; }
    TF_R(13) TF_R(15) TF_R(26) TF_R(6)
    x0 += k1; x1 += k2 + 1u;
    TF_R(17) TF_R(29) TF_R(16) TF_R(24)
    x0 += k2; x1 += k0 + 2u;
    TF_R(13) TF_R(15) TF_R(26) TF_R(6)
    x0 += k0; x1 += k1 + 3u;
    TF_R(17) TF_R(29) TF_R(16) TF_R(24)
    x0 += k1; x1 += k2 + 4u;
    TF_R(13) TF_R(15) TF_R(26) TF_R(6)
    x0 += k2; x1 += k0 + 5u;
#undef TF_R
    return x0 ^ x1;
}
// keep = uniform < 0.5  <=>  bits MSB clear (uniform mantissa = bits >> 9).

// ---------------------------------------------------------------------------
// GEMM NN: C[M,N] = A[M,K] @ B[K,N], fp32, 128x128 tile, 8x8 per thread.
// CAUSAL_K: limit k range to (row_block_end) -- used for P@V where P is
// strictly zero for k >= rounded-up row block end.
// ---------------------------------------------------------------------------
template <bool CAUSAL_K>
__global__ void __launch_bounds__(256) gemm_nn_kernel(
    const float* __restrict__ A, const float* __restrict__ B,
    float* __restrict__ C, int M, int N, int K)
{
    const int BM = 128, BN = 128, BK = 8;
    __shared__ float As[BK][BM];
    __shared__ float Bs[BK][BN];

    int tid = threadIdx.x;
    int row0 = blockIdx.y * BM;
    int col0 = blockIdx.x * BN;
    int kEnd = CAUSAL_K ? (row0 + BM) : K;

    int tx = tid & 15, ty = tid >> 4;

    float acc[8][8];
#pragma unroll
    for (int i = 0; i < 8; i++)
#pragma unroll
        for (int j = 0; j < 8; j++) acc[i][j] = 0.f;

    int aRow = tid >> 1, aCol = (tid & 1) * 4;
    int bRow = tid >> 5, bCol = (tid & 31) * 4;
    const float* Aptr = A + (size_t)(row0 + aRow) * K + aCol;
    const float* Bptr = B + (size_t)bRow * N + col0 + bCol;

    for (int kt = 0; kt < kEnd; kt += BK) {
        float4 av = *(const float4*)(Aptr + kt);
        float4 bv = *(const float4*)(Bptr + (size_t)kt * N);
        __syncthreads();
        As[aCol + 0][aRow] = av.x;
        As[aCol + 1][aRow] = av.y;
        As[aCol + 2][aRow] = av.z;
        As[aCol + 3][aRow] = av.w;
        *(float4*)&Bs[bRow][bCol] = bv;
        __syncthreads();
#pragma unroll
        for (int k = 0; k < BK; k++) {
            float4 a0 = *(float4*)&As[k][ty * 8];
            float4 a1 = *(float4*)&As[k][ty * 8 + 4];
            float4 b0 = *(float4*)&Bs[k][tx * 8];
            float4 b1 = *(float4*)&Bs[k][tx * 8 + 4];
            float ar[8] = {a0.x, a0.y, a0.z, a0.w, a1.x, a1.y, a1.z, a1.w};
            float br[8] = {b0.x, b0.y, b0.z, b0.w, b1.x, b1.y, b1.z, b1.w};
#pragma unroll
            for (int i = 0; i < 8; i++)
#pragma unroll
                for (int j = 0; j < 8; j++) acc[i][j] = fmaf(ar[i], br[j], acc[i][j]);
        }
    }

#pragma unroll
    for (int i = 0; i < 8; i++) {
        float* cp = C + (size_t)(row0 + ty * 8 + i) * N + col0 + tx * 8;
        float4 v0 = {acc[i][0], acc[i][1], acc[i][2], acc[i][3]};
        float4 v1 = {acc[i][4], acc[i][5], acc[i][6], acc[i][7]};
        *(float4*)(cp) = v0;
        *(float4*)(cp + 4) = v1;
    }
}

// ---------------------------------------------------------------------------
// GEMM NT: C[M,N] = A[M,K] @ B[N,K]^T  (scores = Q @ K^T), causal block skip.
// ---------------------------------------------------------------------------
__global__ void __launch_bounds__(256) gemm_nt_causal_kernel(
    const float* __restrict__ A, const float* __restrict__ B,
    float* __restrict__ C, int M, int N, int K)
{
    if (blockIdx.x > blockIdx.y) return;  // block fully above diagonal
    const int BM = 128, BN = 128, BK = 8;
    __shared__ float As[BK][BM];
    __shared__ float Bs[BK][BN];

    int tid = threadIdx.x;
    int row0 = blockIdx.y * BM;
    int col0 = blockIdx.x * BN;
    int tx = tid & 15, ty = tid >> 4;

    float acc[8][8];
#pragma unroll
    for (int i = 0; i < 8; i++)
#pragma unroll
        for (int j = 0; j < 8; j++) acc[i][j] = 0.f;

    int aRow = tid >> 1, aCol = (tid & 1) * 4;
    const float* Aptr = A + (size_t)(row0 + aRow) * K + aCol;
    const float* Bptr = B + (size_t)(col0 + aRow) * K + aCol;

    for (int kt = 0; kt < K; kt += BK) {
        float4 av = *(const float4*)(Aptr + kt);
        float4 bv = *(const float4*)(Bptr + kt);
        __syncthreads();
        As[aCol + 0][aRow] = av.x;
        As[aCol + 1][aRow] = av.y;
        As[aCol + 2][aRow] = av.z;
        As[aCol + 3][aRow] = av.w;
        Bs[aCol + 0][aRow] = bv.x;
        Bs[aCol + 1][aRow] = bv.y;
        Bs[aCol + 2][aRow] = bv.z;
        Bs[aCol + 3][aRow] = bv.w;
        __syncthreads();
#pragma unroll
        for (int k = 0; k < BK; k++) {
            float4 a0 = *(float4*)&As[k][ty * 8];
            float4 a1 = *(float4*)&As[k][ty * 8 + 4];
            float4 b0 = *(float4*)&Bs[k][tx * 8];
            float4 b1 = *(float4*)&Bs[k][tx * 8 + 4];
            float ar[8] = {a0.x, a0.y, a0.z, a0.w, a1.x, a1.y, a1.z, a1.w};
            float br[8] = {b0.x, b0.y, b0.z, b0.w, b1.x, b1.y, b1.z, b1.w};
#pragma unroll
            for (int i = 0; i < 8; i++)
#pragma unroll
                for (int j = 0; j < 8; j++) acc[i][j] = fmaf(ar[i], br[j], acc[i][j]);
        }
    }

#pragma unroll
    for (int i = 0; i < 8; i++) {
        float* cp = C + (size_t)(row0 + ty * 8 + i) * N + col0 + tx * 8;
        float4 v0 = {acc[i][0], acc[i][1], acc[i][2], acc[i][3]};
        float4 v1 = {acc[i][4], acc[i][5], acc[i][6], acc[i][7]};
        *(float4*)(cp) = v0;
        *(float4*)(cp + 4) = v1;
    }
}

// ---------------------------------------------------------------------------
// Per-row softmax + threefry dropout. One block per row. Row (<=16KB) cached
// in smem. Writes normalized*dropout values for j<=i, zeros for
// i < j < rowEnd (128-rounded) so the PV GEMM k-limit sees exact zeros.
// ---------------------------------------------------------------------------
__global__ void __launch_bounds__(256) softmax_dropout_kernel(float* __restrict__ P)
{
    __shared__ float buf[SEQ];
    __shared__ float red[256];
    int i = blockIdx.x;
    int tid = threadIdx.x;
    int L = i + 1;
    int rowEnd = ((i >> 7) + 1) << 7;
    const float inv_scale = 0.022097086912079608f;  // 1/sqrt(2048)
    float* row = P + (size_t)i * SEQ;

    float lmax = -INFINITY;
    for (int j = tid; j < L; j += 256) {
        float v = row[j] * inv_scale;
        buf[j] = v;
        lmax = fmaxf(lmax, v);
    }
    red[tid] = lmax;
    __syncthreads();
#pragma unroll
    for (int s = 128; s > 0; s >>= 1) {
        if (tid < s) red[tid] = fmaxf(red[tid], red[tid + s]);
        __syncthreads();
    }
    float m = red[0];
    __syncthreads();

    float lsum = 0.f;
    for (int j = tid; j < L; j += 256) {
        float e = expf(buf[j] - m);
        buf[j] = e;
        lsum += e;
    }
    red[tid] = lsum;
    __syncthreads();
#pragma unroll
    for (int s = 128; s > 0; s >>= 1) {
        if (tid < s) red[tid] += red[tid + s];
        __syncthreads();
    }
    float invZ2 = 2.0f / red[0];  // 1/Z * 1/(1-p) with p=0.5

    for (int j = tid; j < rowEnd; j += 256) {
        float v = 0.f;
        if (j < L) {
            uint32_t bits = threefry_bits((uint32_t)i * (uint32_t)SEQ + (uint32_t)j);
            if (!(bits & 0x80000000u)) v = buf[j] * invZ2;
        }
        row[j] = v;
    }
}

// ---------------------------------------------------------------------------
extern "C" void kernel_launch(void* const* d_in, const int* in_sizes, int n_in,
                              void* d_out, int out_size)
{
    const float* x  = (const float*)d_in[0];
    const float* Wq = (const float*)d_in[1];
    const float* Wk = (const float*)d_in[2];
    const float* Wv = (const float*)d_in[3];
    float* out = (float*)d_out;

    float *Q, *K, *V, *P;
    cudaGetSymbolAddress((void**)&Q, g_Q);
    cudaGetSymbolAddress((void**)&K, g_K);
    cudaGetSymbolAddress((void**)&V, g_V);
    cudaGetSymbolAddress((void**)&P, g_P);

    dim3 blk(256);
    dim3 gproj(DOUT / 128, SEQ / 128);  // (16, 32)
    gemm_nn_kernel<false><<<gproj, blk>>>(x, Wq, Q, SEQ, DOUT, DIN);
    gemm_nn_kernel<false><<<gproj, blk>>>(x, Wk, K, SEQ, DOUT, DIN);
    gemm_nn_kernel<false><<<gproj, blk>>>(x, Wv, V, SEQ, DOUT, DIN);

    dim3 gsc(SEQ / 128, SEQ / 128);  // (32, 32), upper-triangular blocks early-exit
    gemm_nt_causal_kernel<<<gsc, blk>>>(Q, K, P, SEQ, SEQ, DIN);

    softmax_dropout_kernel<<<SEQ, blk>>>(P);

    dim3 gpv(DOUT / 128, SEQ / 128);
    gemm_nn_kernel<true><<<gpv, blk>>>(P, V, out, SEQ, DOUT, SEQ);
}

// round 9
// speedup vs baseline: 1.1370x; 1.1370x over previous
#include <cuda_runtime.h>
#include <math.h>
#include <stdint.h>

#define SEQ 4096
#define DIN 2048
#define DOUT 2048

// Scratch (static device globals -- no allocation at runtime)
__device__ float g_Q[SEQ * DOUT];
__device__ float g_K[SEQ * DOUT];
__device__ float g_V[SEQ * DOUT];
__device__ float g_P[(size_t)SEQ * SEQ];

__device__ __forceinline__ uint32_t rotl32(uint32_t x, int d) {
    return __funnelshift_l(x, x, d);
}

// JAX threefry2x32, PARTITIONABLE scheme. key=(0,42); counter=(0, idx);
// 32-bit output = o0 ^ o1. keep = MSB clear (u < 0.5).
__device__ __forceinline__ uint32_t threefry_bits(uint32_t idx) {
    const uint32_t k0 = 0u, k1 = 42u;
    const uint32_t k2 = 0x1BD11BDAu ^ k0 ^ k1;
    uint32_t x0 = 0u + k0, x1 = idx + k1;
#define TF_R(r) { x0 += x1; x1 = rotl32(x1, (r)); x1 ^= x0; }
    TF_R(13) TF_R(15) TF_R(26) TF_R(6)
    x0 += k1; x1 += k2 + 1u;
    TF_R(17) TF_R(29) TF_R(16) TF_R(24)
    x0 += k2; x1 += k0 + 2u;
    TF_R(13) TF_R(15) TF_R(26) TF_R(6)
    x0 += k0; x1 += k1 + 3u;
    TF_R(17) TF_R(29) TF_R(16) TF_R(24)
    x0 += k1; x1 += k2 + 4u;
    TF_R(13) TF_R(15) TF_R(26) TF_R(6)
    x0 += k2; x1 += k0 + 5u;
#undef TF_R
    return x0 ^ x1;
}

// ---------------------------------------------------------------------------
// Unified pipelined GEMM: C[M,N] = A[M,K] @ op(B), fp32.
//   NT=false: B is [K,N] (op(B)=B)      -- projections, P@V
//   NT=true : B is [N,K] (op(B)=B^T)    -- scores Q@K^T
//   CAUSAL_K: k-range limited to row-block end (P@V: P zero beyond diag block)
//   CAUSAL_SKIP: skip blocks fully above diagonal (Q@K^T)
// 128x128 tile, BK=16, 2-stage smem double buffer (1 sync/iter), LDG
// prefetch in regs, fragment double-buffer in the k-loop. 8x8 per thread.
// ---------------------------------------------------------------------------
template <bool NT, bool CAUSAL_K, bool CAUSAL_SKIP>
__global__ void __launch_bounds__(256, 2) gemm_kernel(
    const float* __restrict__ A, const float* __restrict__ B,
    float* __restrict__ C, int M, int N, int K)
{
    if (CAUSAL_SKIP && blockIdx.x > blockIdx.y) return;
    const int BM = 128, BN = 128, BK = 16;
    __shared__ float As[2][BK][BM];
    __shared__ float Bs[2][BK][BN];

    int tid = threadIdx.x;
    int row0 = blockIdx.y * BM;
    int col0 = blockIdx.x * BN;
    int kEnd = CAUSAL_K ? (row0 + BM) : K;

    int tx = tid & 15, ty = tid >> 4;

    float acc[8][8];
#pragma unroll
    for (int i = 0; i < 8; i++)
#pragma unroll
        for (int j = 0; j < 8; j++) acc[i][j] = 0.f;

    // A tile load mapping: 128 rows x 16 k. Each thread: 1 row, 8 k (2 float4).
    int aRow = tid >> 1, aCol = (tid & 1) * 8;
    const float* Aptr = A + (size_t)(row0 + aRow) * K + aCol;

    // B tile load mapping.
    const float* Bptr;
    int bRow = 0, bCol = 0;
    if (NT) {
        // B[N,K]: same transpose pattern as A (rows of B = cols of C).
        Bptr = B + (size_t)(col0 + aRow) * K + aCol;
    } else {
        // B[K,N]: 16 k-rows x 128 cols. 32 threads/row x float4 = 128 cols;
        // each thread covers rows bRow and bRow+8 (bRow in [0,8)).
        bRow = tid >> 5; bCol = (tid & 31) * 4;
        Bptr = B + (size_t)bRow * N + col0 + bCol;
    }

    float4 la0, la1, lb0, lb1;

    // --- load tile 0 ---
    la0 = *(const float4*)(Aptr + 0);
    la1 = *(const float4*)(Aptr + 4);
    if (NT) {
        lb0 = *(const float4*)(Bptr + 0);
        lb1 = *(const float4*)(Bptr + 4);
    } else {
        lb0 = *(const float4*)(Bptr + 0);
        lb1 = *(const float4*)(Bptr + (size_t)8 * N);
    }
    {
        float* as = &As[0][0][0];
        as[(aCol + 0) * BM + aRow] = la0.x;
        as[(aCol + 1) * BM + aRow] = la0.y;
        as[(aCol + 2) * BM + aRow] = la0.z;
        as[(aCol + 3) * BM + aRow] = la0.w;
        as[(aCol + 4) * BM + aRow] = la1.x;
        as[(aCol + 5) * BM + aRow] = la1.y;
        as[(aCol + 6) * BM + aRow] = la1.z;
        as[(aCol + 7) * BM + aRow] = la1.w;
        if (NT) {
            float* bs = &Bs[0][0][0];
            bs[(aCol + 0) * BN + aRow] = lb0.x;
            bs[(aCol + 1) * BN + aRow] = lb0.y;
            bs[(aCol + 2) * BN + aRow] = lb0.z;
            bs[(aCol + 3) * BN + aRow] = lb0.w;
            bs[(aCol + 4) * BN + aRow] = lb1.x;
            bs[(aCol + 5) * BN + aRow] = lb1.y;
            bs[(aCol + 6) * BN + aRow] = lb1.z;
            bs[(aCol + 7) * BN + aRow] = lb1.w;
        } else {
            *(float4*)&Bs[0][bRow][bCol] = lb0;
            *(float4*)&Bs[0][bRow + 8][bCol] = lb1;
        }
    }
    __syncthreads();

    int s = 0;
    for (int kt = 0; kt < kEnd; kt += BK) {
        bool has_next = (kt + BK) < kEnd;
        // prefetch next tile into registers (latency hidden under compute)
        if (has_next) {
            int kn = kt + BK;
            la0 = *(const float4*)(Aptr + kn);
            la1 = *(const float4*)(Aptr + kn + 4);
            if (NT) {
                lb0 = *(const float4*)(Bptr + kn);
                lb1 = *(const float4*)(Bptr + kn + 4);
            } else {
                lb0 = *(const float4*)(Bptr + (size_t)kn * N);
                lb1 = *(const float4*)(Bptr + (size_t)(kn + 8) * N);
            }
        }

        // compute on stage s with fragment double-buffer
        {
            const float* as = &As[s][0][0];
            const float* bs = &Bs[s][0][0];
            float4 A0 = *(const float4*)(as + ty * 8);
            float4 A1 = *(const float4*)(as + ty * 8 + 4);
            float4 B0 = *(const float4*)(bs + tx * 8);
            float4 B1 = *(const float4*)(bs + tx * 8 + 4);
#pragma unroll
            for (int k = 0; k < BK; k++) {
                float4 A0n, A1n, B0n, B1n;
                if (k < BK - 1) {
                    A0n = *(const float4*)(as + (k + 1) * BM + ty * 8);
                    A1n = *(const float4*)(as + (k + 1) * BM + ty * 8 + 4);
                    B0n = *(const float4*)(bs + (k + 1) * BN + tx * 8);
                    B1n = *(const float4*)(bs + (k + 1) * BN + tx * 8 + 4);
                }
                float ar[8] = {A0.x, A0.y, A0.z, A0.w, A1.x, A1.y, A1.z, A1.w};
                float br[8] = {B0.x, B0.y, B0.z, B0.w, B1.x, B1.y, B1.z, B1.w};
#pragma unroll
                for (int i = 0; i < 8; i++)
#pragma unroll
                    for (int j = 0; j < 8; j++)
                        acc[i][j] = fmaf(ar[i], br[j], acc[i][j]);
                if (k < BK - 1) { A0 = A0n; A1 = A1n; B0 = B0n; B1 = B1n; }
            }
        }

        if (has_next) {
            // write prefetched tile into the other stage; its last readers
            // were ordered by the sync at the end of the previous iteration.
            int ns = s ^ 1;
            float* as = &As[ns][0][0];
            as[(aCol + 0) * BM + aRow] = la0.x;
            as[(aCol + 1) * BM + aRow] = la0.y;
            as[(aCol + 2) * BM + aRow] = la0.z;
            as[(aCol + 3) * BM + aRow] = la0.w;
            as[(aCol + 4) * BM + aRow] = la1.x;
            as[(aCol + 5) * BM + aRow] = la1.y;
            as[(aCol + 6) * BM + aRow] = la1.z;
            as[(aCol + 7) * BM + aRow] = la1.w;
            if (NT) {
                float* bs = &Bs[ns][0][0];
                bs[(aCol + 0) * BN + aRow] = lb0.x;
                bs[(aCol + 1) * BN + aRow] = lb0.y;
                bs[(aCol + 2) * BN + aRow] = lb0.z;
                bs[(aCol + 3) * BN + aRow] = lb0.w;
                bs[(aCol + 4) * BN + aRow] = lb1.x;
                bs[(aCol + 5) * BN + aRow] = lb1.y;
                bs[(aCol + 6) * BN + aRow] = lb1.z;
                bs[(aCol + 7) * BN + aRow] = lb1.w;
            } else {
                *(float4*)&Bs[ns][bRow][bCol] = lb0;
                *(float4*)&Bs[ns][bRow + 8][bCol] = lb1;
            }
            __syncthreads();
            s = ns;
        }
    }

#pragma unroll
    for (int i = 0; i < 8; i++) {
        float* cp = C + (size_t)(row0 + ty * 8 + i) * N + col0 + tx * 8;
        float4 v0 = {acc[i][0], acc[i][1], acc[i][2], acc[i][3]};
        float4 v1 = {acc[i][4], acc[i][5], acc[i][6], acc[i][7]};
        *(float4*)(cp) = v0;
        *(float4*)(cp + 4) = v1;
    }
}

// ---------------------------------------------------------------------------
// Per-row softmax + threefry dropout. One block per row. Writes normalized
// dropout values for j<=i, zeros up to the 128-rounded row end so the PV
// GEMM k-limit sees exact zeros.
// ---------------------------------------------------------------------------
__global__ void __launch_bounds__(256) softmax_dropout_kernel(float* __restrict__ P)
{
    __shared__ float buf[SEQ];
    __shared__ float red[256];
    int i = blockIdx.x;
    int tid = threadIdx.x;
    int L = i + 1;
    int rowEnd = ((i >> 7) + 1) << 7;
    const float inv_scale = 0.022097086912079608f;  // 1/sqrt(2048)
    float* row = P + (size_t)i * SEQ;

    float lmax = -INFINITY;
    for (int j = tid; j < L; j += 256) {
        float v = row[j] * inv_scale;
        buf[j] = v;
        lmax = fmaxf(lmax, v);
    }
    red[tid] = lmax;
    __syncthreads();
#pragma unroll
    for (int s = 128; s > 0; s >>= 1) {
        if (tid < s) red[tid] = fmaxf(red[tid], red[tid + s]);
        __syncthreads();
    }
    float m = red[0];
    __syncthreads();

    float lsum = 0.f;
    for (int j = tid; j < L; j += 256) {
        float e = expf(buf[j] - m);
        buf[j] = e;
        lsum += e;
    }
    red[tid] = lsum;
    __syncthreads();
#pragma unroll
    for (int s = 128; s > 0; s >>= 1) {
        if (tid < s) red[tid] += red[tid + s];
        __syncthreads();
    }
    float invZ2 = 2.0f / red[0];  // 1/Z * 1/(1-p), p=0.5

    for (int j = tid; j < rowEnd; j += 256) {
        float v = 0.f;
        if (j < L) {
            uint32_t bits = threefry_bits((uint32_t)i * (uint32_t)SEQ + (uint32_t)j);
            if (!(bits & 0x80000000u)) v = buf[j] * invZ2;
        }
        row[j] = v;
    }
}

// ---------------------------------------------------------------------------
extern "C" void kernel_launch(void* const* d_in, const int* in_sizes, int n_in,
                              void* d_out, int out_size)
{
    const float* x  = (const float*)d_in[0];
    const float* Wq = (const float*)d_in[1];
    const float* Wk = (const float*)d_in[2];
    const float* Wv = (const float*)d_in[3];
    float* out = (float*)d_out;

    float *Q, *K, *V, *P;
    cudaGetSymbolAddress((void**)&Q, g_Q);
    cudaGetSymbolAddress((void**)&K, g_K);
    cudaGetSymbolAddress((void**)&V, g_V);
    cudaGetSymbolAddress((void**)&P, g_P);

    dim3 blk(256);
    dim3 gproj(DOUT / 128, SEQ / 128);  // (16, 32)
    gemm_kernel<false, false, false><<<gproj, blk>>>(x, Wq, Q, SEQ, DOUT, DIN);
    gemm_kernel<false, false, false><<<gproj, blk>>>(x, Wk, K, SEQ, DOUT, DIN);
    gemm_kernel<false, false, false><<<gproj, blk>>>(x, Wv, V, SEQ, DOUT, DIN);

    dim3 gsc(SEQ / 128, SEQ / 128);  // (32, 32), upper blocks early-exit
    gemm_kernel<true, false, true><<<gsc, blk>>>(Q, K, P, SEQ, SEQ, DIN);

    softmax_dropout_kernel<<<SEQ, blk>>>(P);

    dim3 gpv(DOUT / 128, SEQ / 128);
    gemm_kernel<false, true, false><<<gpv, blk>>>(P, V, out, SEQ, DOUT, SEQ);
}

// round 11
// speedup vs baseline: 1.2016x; 1.0568x over previous
#include <cuda_runtime.h>
#include <math.h>
#include <stdint.h>

#define SEQ 4096
#define DIN 2048
#define DOUT 2048

// Scratch (static device globals -- no allocation at runtime)
__device__ float g_Q[SEQ * DOUT];
__device__ float g_K[SEQ * DOUT];
__device__ float g_V[SEQ * DOUT];
__device__ float g_P[(size_t)SEQ * SEQ];

__device__ __forceinline__ uint32_t rotl32(uint32_t x, int d) {
    return __funnelshift_l(x, x, d);
}

// JAX threefry2x32, PARTITIONABLE scheme. key=(0,42); counter=(0, idx);
// 32-bit output = o0 ^ o1. keep = MSB clear (u < 0.5).
__device__ __forceinline__ uint32_t threefry_bits(uint32_t idx) {
    const uint32_t k0 = 0u, k1 = 42u;
    const uint32_t k2 = 0x1BD11BDAu ^ k0 ^ k1;
    uint32_t x0 = 0u + k0, x1 = idx + k1;
#define TF_R(r) { x0 += x1; x1 = rotl32(x1, (r)); x1 ^= x0; }
    TF_R(13) TF_R(15) TF_R(26) TF_R(6)
    x0 += k1; x1 += k2 + 1u;
    TF_R(17) TF_R(29) TF_R(16) TF_R(24)
    x0 += k2; x1 += k0 + 2u;
    TF_R(13) TF_R(15) TF_R(26) TF_R(6)
    x0 += k0; x1 += k1 + 3u;
    TF_R(17) TF_R(29) TF_R(16) TF_R(24)
    x0 += k1; x1 += k2 + 4u;
    TF_R(13) TF_R(15) TF_R(26) TF_R(6)
    x0 += k2; x1 += k0 + 5u;
#undef TF_R
    return x0 ^ x1;
}

// ---------------------------------------------------------------------------
// Unified pipelined GEMM: C[M,N] = A[M,K] @ op(B), fp32.
//   NT=false: B is [K,N]   -- projections, P@V
//   NT=true : B is [N,K]^T -- scores Q@K^T
//   CAUSAL_K: k-range limited to row-block end (P@V)
//   CAUSAL_SKIP: skip blocks fully above diagonal (Q@K^T)
// 128x128 tile, BK=16, 2-stage smem double buffer, LDG prefetch in regs,
// fragment double-buffer. Per-thread 8x8 output SPLIT as rows {ty*4, 64+ty*4}
// x cols {tx*4, 64+tx*4} so LDS.128 fragment loads are 16B-strided and
// bank-conflict-free (the 32B-strided layout was 2-way conflicted).
// ---------------------------------------------------------------------------
template <bool NT, bool CAUSAL_K, bool CAUSAL_SKIP>
__global__ void __launch_bounds__(256, 2) gemm_kernel(
    const float* __restrict__ A, const float* __restrict__ B,
    float* __restrict__ C, int M, int N, int K)
{
    if (CAUSAL_SKIP && blockIdx.x > blockIdx.y) return;
    const int BM = 128, BN = 128, BK = 16;
    __shared__ float As[2][BK][BM];
    __shared__ float Bs[2][BK][BN];

    int tid = threadIdx.x;
    int row0 = blockIdx.y * BM;
    int col0 = blockIdx.x * BN;
    int kEnd = CAUSAL_K ? (row0 + BM) : K;

    int tx = tid & 15, ty = tid >> 4;

    float acc[8][8];
#pragma unroll
    for (int i = 0; i < 8; i++)
#pragma unroll
        for (int j = 0; j < 8; j++) acc[i][j] = 0.f;

    // A tile load mapping: 128 rows x 16 k. Each thread: 1 row, 8 k (2 float4).
    int aRow = tid >> 1, aCol = (tid & 1) * 8;
    const float* Aptr = A + (size_t)(row0 + aRow) * K + aCol;

    // B tile load mapping.
    const float* Bptr;
    int bRow = 0, bCol = 0;
    if (NT) {
        Bptr = B + (size_t)(col0 + aRow) * K + aCol;
    } else {
        // B[K,N]: 16 k-rows x 128 cols; thread covers rows bRow, bRow+8.
        bRow = tid >> 5; bCol = (tid & 31) * 4;
        Bptr = B + (size_t)bRow * N + col0 + bCol;
    }

    float4 la0, la1, lb0, lb1;

    // --- load tile 0 ---
    la0 = *(const float4*)(Aptr + 0);
    la1 = *(const float4*)(Aptr + 4);
    if (NT) {
        lb0 = *(const float4*)(Bptr + 0);
        lb1 = *(const float4*)(Bptr + 4);
    } else {
        lb0 = *(const float4*)(Bptr + 0);
        lb1 = *(const float4*)(Bptr + (size_t)8 * N);
    }
    {
        float* as = &As[0][0][0];
        as[(aCol + 0) * BM + aRow] = la0.x;
        as[(aCol + 1) * BM + aRow] = la0.y;
        as[(aCol + 2) * BM + aRow] = la0.z;
        as[(aCol + 3) * BM + aRow] = la0.w;
        as[(aCol + 4) * BM + aRow] = la1.x;
        as[(aCol + 5) * BM + aRow] = la1.y;
        as[(aCol + 6) * BM + aRow] = la1.z;
        as[(aCol + 7) * BM + aRow] = la1.w;
        if (NT) {
            float* bs = &Bs[0][0][0];
            bs[(aCol + 0) * BN + aRow] = lb0.x;
            bs[(aCol + 1) * BN + aRow] = lb0.y;
            bs[(aCol + 2) * BN + aRow] = lb0.z;
            bs[(aCol + 3) * BN + aRow] = lb0.w;
            bs[(aCol + 4) * BN + aRow] = lb1.x;
            bs[(aCol + 5) * BN + aRow] = lb1.y;
            bs[(aCol + 6) * BN + aRow] = lb1.z;
            bs[(aCol + 7) * BN + aRow] = lb1.w;
        } else {
            *(float4*)&Bs[0][bRow][bCol] = lb0;
            *(float4*)&Bs[0][bRow + 8][bCol] = lb1;
        }
    }
    __syncthreads();

    int s = 0;
    for (int kt = 0; kt < kEnd; kt += BK) {
        bool has_next = (kt + BK) < kEnd;
        if (has_next) {
            int kn = kt + BK;
            la0 = *(const float4*)(Aptr + kn);
            la1 = *(const float4*)(Aptr + kn + 4);
            if (NT) {
                lb0 = *(const float4*)(Bptr + kn);
                lb1 = *(const float4*)(Bptr + kn + 4);
            } else {
                lb0 = *(const float4*)(Bptr + (size_t)kn * N);
                lb1 = *(const float4*)(Bptr + (size_t)(kn + 8) * N);
            }
        }

        // compute on stage s with fragment double-buffer; fragments at
        // 16B stride (tx*4 / ty*4) + 64-offset halves: conflict-free.
        {
            const float* as = &As[s][0][0];
            const float* bs = &Bs[s][0][0];
            float4 A0 = *(const float4*)(as + ty * 4);
            float4 A1 = *(const float4*)(as + 64 + ty * 4);
            float4 B0 = *(const float4*)(bs + tx * 4);
            float4 B1 = *(const float4*)(bs + 64 + tx * 4);
#pragma unroll
            for (int k = 0; k < BK; k++) {
                float4 A0n, A1n, B0n, B1n;
                if (k < BK - 1) {
                    A0n = *(const float4*)(as + (k + 1) * BM + ty * 4);
                    A1n = *(const float4*)(as + (k + 1) * BM + 64 + ty * 4);
                    B0n = *(const float4*)(bs + (k + 1) * BN + tx * 4);
                    B1n = *(const float4*)(bs + (k + 1) * BN + 64 + tx * 4);
                }
                float ar[8] = {A0.x, A0.y, A0.z, A0.w, A1.x, A1.y, A1.z, A1.w};
                float br[8] = {B0.x, B0.y, B0.z, B0.w, B1.x, B1.y, B1.z, B1.w};
#pragma unroll
                for (int i = 0; i < 8; i++)
#pragma unroll
                    for (int j = 0; j < 8; j++)
                        acc[i][j] = fmaf(ar[i], br[j], acc[i][j]);
                if (k < BK - 1) { A0 = A0n; A1 = A1n; B0 = B0n; B1 = B1n; }
            }
        }

        if (has_next) {
            int ns = s ^ 1;
            float* as = &As[ns][0][0];
            as[(aCol + 0) * BM + aRow] = la0.x;
            as[(aCol + 1) * BM + aRow] = la0.y;
            as[(aCol + 2) * BM + aRow] = la0.z;
            as[(aCol + 3) * BM + aRow] = la0.w;
            as[(aCol + 4) * BM + aRow] = la1.x;
            as[(aCol + 5) * BM + aRow] = la1.y;
            as[(aCol + 6) * BM + aRow] = la1.z;
            as[(aCol + 7) * BM + aRow] = la1.w;
            if (NT) {
                float* bs = &Bs[ns][0][0];
                bs[(aCol + 0) * BN + aRow] = lb0.x;
                bs[(aCol + 1) * BN + aRow] = lb0.y;
                bs[(aCol + 2) * BN + aRow] = lb0.z;
                bs[(aCol + 3) * BN + aRow] = lb0.w;
                bs[(aCol + 4) * BN + aRow] = lb1.x;
                bs[(aCol + 5) * BN + aRow] = lb1.y;
                bs[(aCol + 6) * BN + aRow] = lb1.z;
                bs[(aCol + 7) * BN + aRow] = lb1.w;
            } else {
                *(float4*)&Bs[ns][bRow][bCol] = lb0;
                *(float4*)&Bs[ns][bRow + 8][bCol] = lb1;
            }
            __syncthreads();
            s = ns;
        }
    }

    // Epilogue: acc[i][j] -> row (i<4 ? ty*4+i : 64+ty*4+i-4),
    //                        col (j<4 ? tx*4+j : 64+tx*4+j-4).
#pragma unroll
    for (int i = 0; i < 4; i++) {
        float* cp0 = C + (size_t)(row0 + ty * 4 + i) * N + col0;
        float4 v0 = {acc[i][0], acc[i][1], acc[i][2], acc[i][3]};
        float4 v1 = {acc[i][4], acc[i][5], acc[i][6], acc[i][7]};
        *(float4*)(cp0 + tx * 4) = v0;
        *(float4*)(cp0 + 64 + tx * 4) = v1;
        float* cp1 = C + (size_t)(row0 + 64 + ty * 4 + i) * N + col0;
        float4 w0 = {acc[4 + i][0], acc[4 + i][1], acc[4 + i][2], acc[4 + i][3]};
        float4 w1 = {acc[4 + i][4], acc[4 + i][5], acc[4 + i][6], acc[4 + i][7]};
        *(float4*)(cp1 + tx * 4) = w0;
        *(float4*)(cp1 + 64 + tx * 4) = w1;
    }
}

// ---------------------------------------------------------------------------
// Per-row softmax + threefry dropout. One block per row. Writes normalized
// dropout values for j<=i, zeros up to the 128-rounded row end so the PV
// GEMM k-limit sees exact zeros.
// ---------------------------------------------------------------------------
__global__ void __launch_bounds__(256) softmax_dropout_kernel(float* __restrict__ P)
{
    __shared__ float buf[SEQ];
    __shared__ float red[256];
    int i = blockIdx.x;
    int tid = threadIdx.x;
    int L = i + 1;
    int rowEnd = ((i >> 7) + 1) << 7;
    const float inv_scale = 0.022097086912079608f;  // 1/sqrt(2048)
    float* row = P + (size_t)i * SEQ;

    float lmax = -INFINITY;
    for (int j = tid; j < L; j += 256) {
        float v = row[j] * inv_scale;
        buf[j] = v;
        lmax = fmaxf(lmax, v);
    }
    red[tid] = lmax;
    __syncthreads();
#pragma unroll
    for (int s = 128; s > 0; s >>= 1) {
        if (tid < s) red[tid] = fmaxf(red[tid], red[tid + s]);
        __syncthreads();
    }
    float m = red[0];
    __syncthreads();

    float lsum = 0.f;
    for (int j = tid; j < L; j += 256) {
        float e = expf(buf[j] - m);
        buf[j] = e;
        lsum += e;
    }
    red[tid] = lsum;
    __syncthreads();
#pragma unroll
    for (int s = 128; s > 0; s >>= 1) {
        if (tid < s) red[tid] += red[tid + s];
        __syncthreads();
    }
    float invZ2 = 2.0f / red[0];  // 1/Z * 1/(1-p), p=0.5

    for (int j = tid; j < rowEnd; j += 256) {
        float v = 0.f;
        if (j < L) {
            uint32_t bits = threefry_bits((uint32_t)i * (uint32_t)SEQ + (uint32_t)j);
            if (!(bits & 0x80000000u)) v = buf[j] * invZ2;
        }
        row[j] = v;
    }
}

// ---------------------------------------------------------------------------
extern "C" void kernel_launch(void* const* d_in, const int* in_sizes, int n_in,
                              void* d_out, int out_size)
{
    const float* x  = (const float*)d_in[0];
    const float* Wq = (const float*)d_in[1];
    const float* Wk = (const float*)d_in[2];
    const float* Wv = (const float*)d_in[3];
    float* out = (float*)d_out;

    float *Q, *K, *V, *P;
    cudaGetSymbolAddress((void**)&Q, g_Q);
    cudaGetSymbolAddress((void**)&K, g_K);
    cudaGetSymbolAddress((void**)&V, g_V);
    cudaGetSymbolAddress((void**)&P, g_P);

    dim3 blk(256);
    dim3 gproj(DOUT / 128, SEQ / 128);  // (16, 32)
    gemm_kernel<false, false, false><<<gproj, blk>>>(x, Wq, Q, SEQ, DOUT, DIN);
    gemm_kernel<false, false, false><<<gproj, blk>>>(x, Wk, K, SEQ, DOUT, DIN);
    gemm_kernel<false, false, false><<<gproj, blk>>>(x, Wv, V, SEQ, DOUT, DIN);

    dim3 gsc(SEQ / 128, SEQ / 128);  // (32, 32), upper blocks early-exit
    gemm_kernel<true, false, true><<<gsc, blk>>>(Q, K, P, SEQ, SEQ, DIN);

    softmax_dropout_kernel<<<SEQ, blk>>>(P);

    dim3 gpv(DOUT / 128, SEQ / 128);
    gemm_kernel<false, true, false><<<gpv, blk>>>(P, V, out, SEQ, DOUT, SEQ);
}

// round 15
// speedup vs baseline: 2.0015x; 1.6656x over previous
#include <cuda_runtime.h>
#include <cuda_bf16.h>
#include <math.h>
#include <stdint.h>

#define SEQ 4096
#define DIN 2048
#define DOUT 2048

typedef __nv_bfloat16 bf16;

// ---------------- scratch (static device globals; zero runtime alloc) -------
__device__ bf16 g_xh[SEQ * DIN],  g_xl[SEQ * DIN];
__device__ bf16 g_Wqh[DOUT * DIN], g_Wql[DOUT * DIN];   // W^T [N,K]
__device__ bf16 g_Wkh[DOUT * DIN], g_Wkl[DOUT * DIN];
__device__ bf16 g_Wvh[DOUT * DIN], g_Wvl[DOUT * DIN];
__device__ float g_Q[SEQ * DOUT], g_K[SEQ * DOUT], g_V[SEQ * DOUT];
__device__ bf16 g_Qh[SEQ * DOUT], g_Ql[SEQ * DOUT];
__device__ bf16 g_Kh[SEQ * DOUT], g_Kl[SEQ * DOUT];
__device__ bf16 g_VTh[DOUT * SEQ], g_VTl[DOUT * SEQ];   // V^T [d, S]
__device__ float g_S[(size_t)SEQ * SEQ];                 // fp32 scores
__device__ bf16 g_Ph[(size_t)SEQ * SEQ], g_Pl[(size_t)SEQ * SEQ];

// ---------------- baseline-PTX helpers (NO sm_103a-gated features) ----------
__device__ __forceinline__ uint32_t smem_u32(const void* p) {
    uint32_t a;
    asm("{ .reg .u64 t; cvta.to.shared.u64 t, %1; cvt.u32.u64 %0, t; }"
        : "=r"(a) : "l"(p));
    return a;
}
__device__ __forceinline__ void cp16(uint32_t dst, const void* src) {
    asm volatile("cp.async.cg.shared.global [%0], [%1], 16;"
                 :: "r"(dst), "l"(src) : "memory");
}
#define CP_COMMIT() asm volatile("cp.async.commit_group;" ::: "memory")
#define CP_WAIT1() asm volatile("cp.async.wait_group 1;" ::: "memory")
#define CP_WAIT0() asm volatile("cp.async.wait_group 0;" ::: "memory")

#define LDSM_X4(r0, r1, r2, r3, addr)                                          \
    asm volatile("ldmatrix.sync.aligned.m8n8.x4.shared.b16 {%0,%1,%2,%3}, [%4];" \
                 : "=r"(r0), "=r"(r1), "=r"(r2), "=r"(r3) : "r"(addr))

#define MMA_BF16(d, a, b)                                                      \
    asm volatile("mma.sync.aligned.m16n8k16.row.col.f32.bf16.bf16.f32 "        \
                 "{%0,%1,%2,%3}, {%4,%5,%6,%7}, {%8,%9}, {%0,%1,%2,%3};"       \
                 : "+f"((d)[0]), "+f"((d)[1]), "+f"((d)[2]), "+f"((d)[3])      \
                 : "r"((a)[0]), "r"((a)[1]), "r"((a)[2]), "r"((a)[3]),         \
                   "r"((b)[0]), "r"((b)[1]))

// ---------------- threefry (JAX partitionable, key=(0,42)) ------------------
__device__ __forceinline__ uint32_t rotl32(uint32_t x, int d) {
    return __funnelshift_l(x, x, d);
}
__device__ __forceinline__ uint32_t threefry_bits(uint32_t idx) {
    const uint32_t k0 = 0u, k1 = 42u;
    const uint32_t k2 = 0x1BD11BDAu ^ k0 ^ k1;
    uint32_t x0 = 0u + k0, x1 = idx + k1;
#define TF_R(r) { x0 += x1; x1 = rotl32(x1, (r)); x1 ^= x0; }
    TF_R(13) TF_R(15) TF_R(26) TF_R(6)
    x0 += k1; x1 += k2 + 1u;
    TF_R(17) TF_R(29) TF_R(16) TF_R(24)
    x0 += k2; x1 += k0 + 2u;
    TF_R(13) TF_R(15) TF_R(26) TF_R(6)
    x0 += k0; x1 += k1 + 3u;
    TF_R(17) TF_R(29) TF_R(16) TF_R(24)
    x0 += k1; x1 += k2 + 4u;
    TF_R(13) TF_R(15) TF_R(26) TF_R(6)
    x0 += k2; x1 += k0 + 5u;
#undef TF_R
    return x0 ^ x1;
}

// ---------------- convert kernels -------------------------------------------
__global__ void __launch_bounds__(256) split_kernel(
    const float* __restrict__ in, bf16* __restrict__ hi, bf16* __restrict__ lo, int n)
{
    int i = blockIdx.x * 256 + threadIdx.x;
    if (i < n) {
        float v = in[i];
        bf16 h = __float2bfloat16(v);
        hi[i] = h;
        lo[i] = __float2bfloat16(v - __bfloat162float(h));
    }
}

// in [R, C] fp32 -> hi/lo [C, R] bf16
__global__ void __launch_bounds__(256) transpose_split_kernel(
    const float* __restrict__ in, bf16* __restrict__ hi, bf16* __restrict__ lo,
    int R, int C)
{
    __shared__ float t[32][33];
    int tx = threadIdx.x, ty = threadIdx.y;
    int x = blockIdx.x * 32 + tx;
    int y0 = blockIdx.y * 32;
#pragma unroll
    for (int j = 0; j < 4; j++)
        t[ty + 8 * j][tx] = in[(size_t)(y0 + ty + 8 * j) * C + x];
    __syncthreads();
    int ox = y0 + tx;
    int oy0 = blockIdx.x * 32;
#pragma unroll
    for (int j = 0; j < 4; j++) {
        float v = t[tx][ty + 8 * j];
        bf16 h = __float2bfloat16(v);
        size_t o = (size_t)(oy0 + ty + 8 * j) * R + ox;
        hi[o] = h;
        lo[o] = __float2bfloat16(v - __bfloat162float(h));
    }
}

// ---------------- mma.sync split-bf16 GEMM ----------------------------------
// C[M,N] = (Ah+Al)[M,K] @ (Bh+Bl)[N,K]^T  (3 products, fp32 accum)
// CTA 128x128, 8 warps (32m x 64n each), BK=16, cp.async 2-stage pipeline.
// Smem rows padded to 48B: ldmatrix phases (8 rows x 16B) hit 8 distinct
// 16B slots -> conflict-free.
static constexpr int ROWB = 48;                    // bytes per smem row
static constexpr int OPB  = 128 * ROWB;            // 6144 B per operand tile
static constexpr int STAGE = 4 * OPB;              // Ah,Al,Bh,Bl
template <bool CAUSAL_K, bool CAUSAL_SKIP>
__global__ void __launch_bounds__(256) gemm_mma_kernel(
    const bf16* __restrict__ Ah, const bf16* __restrict__ Al,
    const bf16* __restrict__ Bh, const bf16* __restrict__ Bl,
    float* __restrict__ C, int M, int N, int K)
{
    if (CAUSAL_SKIP && blockIdx.x > blockIdx.y) return;
    __shared__ char smem[2 * STAGE];
    const uint32_t sbase = smem_u32(smem);
    const int tid = threadIdx.x;
    const int lane = tid & 31;
    const int wid = tid >> 5;
    const int wm = wid >> 1;          // 0..3 -> rows wm*32
    const int wn = wid & 1;           // 0..1 -> cols wn*64
    const int row0 = blockIdx.y * 128;
    const int col0 = blockIdx.x * 128;
    const int kEnd = CAUSAL_K ? (row0 + 128) : K;
    const int nch = kEnd >> 4;        // chunks of 16

    // loader mapping: row r (0..127), 16B half h
    const int r = tid >> 1, h = tid & 1;
    const bf16* pAh = Ah + (size_t)(row0 + r) * K + h * 8;
    const bf16* pAl = Al + (size_t)(row0 + r) * K + h * 8;
    const bf16* pBh = Bh + (size_t)(col0 + r) * K + h * 8;
    const bf16* pBl = Bl + (size_t)(col0 + r) * K + h * 8;
    const uint32_t dsto = (uint32_t)(r * ROWB + h * 16);

    float acc[2][8][4];
#pragma unroll
    for (int t = 0; t < 2; t++)
#pragma unroll
        for (int j = 0; j < 8; j++)
#pragma unroll
            for (int q = 0; q < 4; q++) acc[t][j][q] = 0.f;

#define ISSUE(c) do {                                                          \
    int _kc = (c) * 16;                                                        \
    uint32_t _d = sbase + ((c) & 1) * STAGE + dsto;                            \
    cp16(_d + 0 * OPB, pAh + _kc);                                             \
    cp16(_d + 1 * OPB, pAl + _kc);                                             \
    cp16(_d + 2 * OPB, pBh + _kc);                                             \
    cp16(_d + 3 * OPB, pBl + _kc);                                             \
} while (0)

    ISSUE(0);
    CP_COMMIT();

    // fragment addresses (fixed per thread)
    const uint32_t a_off = (uint32_t)((wm * 32 + (lane & 15)) * ROWB + (lane >> 4) * 16);
    const uint32_t b_off = (uint32_t)((wn * 64 + (lane & 15)) * ROWB + (lane >> 4) * 16);

    for (int c = 0; c < nch; c++) {
        if (c + 1 < nch) { ISSUE(c + 1); CP_COMMIT(); CP_WAIT1(); }
        else             { CP_WAIT0(); }
        __syncthreads();

        const uint32_t st = sbase + (c & 1) * STAGE;
        uint32_t ah[2][4], al[2][4], bh[8][2], bl[8][2];
#pragma unroll
        for (int t = 0; t < 2; t++) {
            LDSM_X4(ah[t][0], ah[t][1], ah[t][2], ah[t][3],
                    st + 0 * OPB + a_off + t * 16 * ROWB);
            LDSM_X4(al[t][0], al[t][1], al[t][2], al[t][3],
                    st + 1 * OPB + a_off + t * 16 * ROWB);
        }
#pragma unroll
        for (int jj = 0; jj < 4; jj++) {
            uint32_t q0, q1, q2, q3;
            LDSM_X4(q0, q1, q2, q3, st + 2 * OPB + b_off + jj * 16 * ROWB);
            bh[2 * jj][0] = q0; bh[2 * jj][1] = q2;
            bh[2 * jj + 1][0] = q1; bh[2 * jj + 1][1] = q3;
            LDSM_X4(q0, q1, q2, q3, st + 3 * OPB + b_off + jj * 16 * ROWB);
            bl[2 * jj][0] = q0; bl[2 * jj][1] = q2;
            bl[2 * jj + 1][0] = q1; bl[2 * jj + 1][1] = q3;
        }
#pragma unroll
        for (int t = 0; t < 2; t++)
#pragma unroll
            for (int j = 0; j < 8; j++) {
                MMA_BF16(acc[t][j], ah[t], bh[j]);
                MMA_BF16(acc[t][j], ah[t], bl[j]);
                MMA_BF16(acc[t][j], al[t], bh[j]);
            }
        __syncthreads();
    }
#undef ISSUE

    // epilogue: frag (t,j): rows wm*32+t*16+{lane>>2, +8}, cols wn*64+j*8+(lane&3)*2
#pragma unroll
    for (int t = 0; t < 2; t++) {
        int r1 = row0 + wm * 32 + t * 16 + (lane >> 2);
#pragma unroll
        for (int j = 0; j < 8; j++) {
            int cc = col0 + wn * 64 + j * 8 + (lane & 3) * 2;
            float2 v0 = {acc[t][j][0], acc[t][j][1]};
            float2 v1 = {acc[t][j][2], acc[t][j][3]};
            *(float2*)(C + (size_t)r1 * N + cc) = v0;
            *(float2*)(C + (size_t)(r1 + 8) * N + cc) = v1;
        }
    }
}

// ---------------- softmax + dropout + bf16 split ---------------------------
__global__ void __launch_bounds__(256) softmax_dropout_kernel(
    const float* __restrict__ S, bf16* __restrict__ Ph, bf16* __restrict__ Pl)
{
    __shared__ float buf[SEQ];
    __shared__ float red[256];
    int i = blockIdx.x;
    int tid = threadIdx.x;
    int L = i + 1;
    int rowEnd = ((i >> 7) + 1) << 7;
    const float inv_scale = 0.022097086912079608f;  // 1/sqrt(2048)
    const float* row = S + (size_t)i * SEQ;

    float lmax = -INFINITY;
    for (int j = tid; j < L; j += 256) {
        float v = row[j] * inv_scale;
        buf[j] = v;
        lmax = fmaxf(lmax, v);
    }
    red[tid] = lmax;
    __syncthreads();
#pragma unroll
    for (int s = 128; s > 0; s >>= 1) {
        if (tid < s) red[tid] = fmaxf(red[tid], red[tid + s]);
        __syncthreads();
    }
    float m = red[0];
    __syncthreads();

    float lsum = 0.f;
    for (int j = tid; j < L; j += 256) {
        float e = expf(buf[j] - m);
        buf[j] = e;
        lsum += e;
    }
    red[tid] = lsum;
    __syncthreads();
#pragma unroll
    for (int s = 128; s > 0; s >>= 1) {
        if (tid < s) red[tid] += red[tid + s];
        __syncthreads();
    }
    float invZ2 = 2.0f / red[0];  // 1/Z * 1/(1-p), p=0.5

    for (int j = tid; j < rowEnd; j += 256) {
        float v = 0.f;
        if (j < L) {
            uint32_t bits = threefry_bits((uint32_t)i * (uint32_t)SEQ + (uint32_t)j);
            if (!(bits & 0x80000000u)) v = buf[j] * invZ2;
        }
        bf16 hi = __float2bfloat16(v);
        size_t o = (size_t)i * SEQ + j;
        Ph[o] = hi;
        Pl[o] = __float2bfloat16(v - __bfloat162float(hi));
    }
}

// ---------------------------------------------------------------------------
extern "C" void kernel_launch(void* const* d_in, const int* in_sizes, int n_in,
                              void* d_out, int out_size)
{
    const float* x  = (const float*)d_in[0];
    const float* Wq = (const float*)d_in[1];
    const float* Wk = (const float*)d_in[2];
    const float* Wv = (const float*)d_in[3];
    float* out = (float*)d_out;

    bf16 *xh, *xl, *Wqh, *Wql, *Wkh, *Wkl, *Wvh, *Wvl;
    bf16 *Qh, *Ql, *Kh, *Kl, *VTh, *VTl, *Pph, *Ppl;
    float *Q, *K, *V, *S;
    cudaGetSymbolAddress((void**)&xh, g_xh);   cudaGetSymbolAddress((void**)&xl, g_xl);
    cudaGetSymbolAddress((void**)&Wqh, g_Wqh); cudaGetSymbolAddress((void**)&Wql, g_Wql);
    cudaGetSymbolAddress((void**)&Wkh, g_Wkh); cudaGetSymbolAddress((void**)&Wkl, g_Wkl);
    cudaGetSymbolAddress((void**)&Wvh, g_Wvh); cudaGetSymbolAddress((void**)&Wvl, g_Wvl);
    cudaGetSymbolAddress((void**)&Q, g_Q);     cudaGetSymbolAddress((void**)&K, g_K);
    cudaGetSymbolAddress((void**)&V, g_V);     cudaGetSymbolAddress((void**)&S, g_S);
    cudaGetSymbolAddress((void**)&Qh, g_Qh);   cudaGetSymbolAddress((void**)&Ql, g_Ql);
    cudaGetSymbolAddress((void**)&Kh, g_Kh);   cudaGetSymbolAddress((void**)&Kl, g_Kl);
    cudaGetSymbolAddress((void**)&VTh, g_VTh); cudaGetSymbolAddress((void**)&VTl, g_VTl);
    cudaGetSymbolAddress((void**)&Pph, g_Ph);  cudaGetSymbolAddress((void**)&Ppl, g_Pl);

    dim3 blk(256);
    // 1. split x; transpose-split weights
    split_kernel<<<(SEQ * DIN) / 256, blk>>>(x, xh, xl, SEQ * DIN);
    dim3 tblk(32, 8);
    dim3 tgW(DOUT / 32, DIN / 32);
    transpose_split_kernel<<<tgW, tblk>>>(Wq, Wqh, Wql, DIN, DOUT);
    transpose_split_kernel<<<tgW, tblk>>>(Wk, Wkh, Wkl, DIN, DOUT);
    transpose_split_kernel<<<tgW, tblk>>>(Wv, Wvh, Wvl, DIN, DOUT);

    // 2. projections (mma.sync bf16 3-product)
    dim3 gproj(DOUT / 128, SEQ / 128);
    gemm_mma_kernel<false, false><<<gproj, blk>>>(xh, xl, Wqh, Wql, Q, SEQ, DOUT, DIN);
    gemm_mma_kernel<false, false><<<gproj, blk>>>(xh, xl, Wkh, Wkl, K, SEQ, DOUT, DIN);
    gemm_mma_kernel<false, false><<<gproj, blk>>>(xh, xl, Wvh, Wvl, V, SEQ, DOUT, DIN);

    // 3. split Q, K; transpose-split V
    split_kernel<<<(SEQ * DOUT) / 256, blk>>>(Q, Qh, Ql, SEQ * DOUT);
    split_kernel<<<(SEQ * DOUT) / 256, blk>>>(K, Kh, Kl, SEQ * DOUT);
    dim3 tgV(DOUT / 32, SEQ / 32);
    transpose_split_kernel<<<tgV, tblk>>>(V, VTh, VTl, SEQ, DOUT);

    // 4. scores (causal block skip)
    dim3 gsc(SEQ / 128, SEQ / 128);
    gemm_mma_kernel<false, true><<<gsc, blk>>>(Qh, Ql, Kh, Kl, S, SEQ, SEQ, DIN);

    // 5. softmax + dropout + split
    softmax_dropout_kernel<<<SEQ, blk>>>(S, Pph, Ppl);

    // 6. P @ V (k-causal)
    dim3 gpv(DOUT / 128, SEQ / 128);
    gemm_mma_kernel<true, false><<<gpv, blk>>>(Pph, Ppl, VTh, VTl, out, SEQ, DOUT, SEQ);
}

// round 16
// speedup vs baseline: 2.2322x; 1.1153x over previous
#include <cuda_runtime.h>
#include <cuda_bf16.h>
#include <math.h>
#include <stdint.h>

#define SEQ 4096
#define DIN 2048
#define DOUT 2048

typedef __nv_bfloat16 bf16;

// ---------------- scratch (static device globals; zero runtime alloc) -------
__device__ bf16 g_xh[SEQ * DIN],  g_xl[SEQ * DIN];
__device__ bf16 g_Wqh[DOUT * DIN], g_Wql[DOUT * DIN];   // W^T [N,K]
__device__ bf16 g_Wkh[DOUT * DIN], g_Wkl[DOUT * DIN];
__device__ bf16 g_Wvh[DOUT * DIN], g_Wvl[DOUT * DIN];
__device__ float g_V[SEQ * DOUT];
__device__ bf16 g_Qh[SEQ * DOUT], g_Ql[SEQ * DOUT];
__device__ bf16 g_Kh[SEQ * DOUT], g_Kl[SEQ * DOUT];
__device__ bf16 g_VTh[DOUT * SEQ], g_VTl[DOUT * SEQ];   // V^T [d, S]
__device__ float g_S[(size_t)SEQ * SEQ];                 // fp32 scores
__device__ bf16 g_Ph[(size_t)SEQ * SEQ], g_Pl[(size_t)SEQ * SEQ];

// ---------------- baseline-PTX helpers --------------------------------------
__device__ __forceinline__ uint32_t smem_u32(const void* p) {
    uint32_t a;
    asm("{ .reg .u64 t; cvta.to.shared.u64 t, %1; cvt.u32.u64 %0, t; }"
        : "=r"(a) : "l"(p));
    return a;
}
__device__ __forceinline__ void cp16(uint32_t dst, const void* src) {
    asm volatile("cp.async.cg.shared.global [%0], [%1], 16;"
                 :: "r"(dst), "l"(src) : "memory");
}
#define CP_COMMIT() asm volatile("cp.async.commit_group;" ::: "memory")
#define CP_WAIT1() asm volatile("cp.async.wait_group 1;" ::: "memory")

#define LDSM_X4(r0, r1, r2, r3, addr)                                          \
    asm volatile("ldmatrix.sync.aligned.m8n8.x4.shared.b16 {%0,%1,%2,%3}, [%4];" \
                 : "=r"(r0), "=r"(r1), "=r"(r2), "=r"(r3) : "r"(addr))

#define MMA_BF16(d, a, b)                                                      \
    asm volatile("mma.sync.aligned.m16n8k16.row.col.f32.bf16.bf16.f32 "        \
                 "{%0,%1,%2,%3}, {%4,%5,%6,%7}, {%8,%9}, {%0,%1,%2,%3};"       \
                 : "+f"((d)[0]), "+f"((d)[1]), "+f"((d)[2]), "+f"((d)[3])      \
                 : "r"((a)[0]), "r"((a)[1]), "r"((a)[2]), "r"((a)[3]),         \
                   "r"((b)[0]), "r"((b)[1]))

// ---------------- threefry (JAX partitionable, key=(0,42)) ------------------
__device__ __forceinline__ uint32_t rotl32(uint32_t x, int d) {
    return __funnelshift_l(x, x, d);
}
__device__ __forceinline__ uint32_t threefry_bits(uint32_t idx) {
    const uint32_t k0 = 0u, k1 = 42u;
    const uint32_t k2 = 0x1BD11BDAu ^ k0 ^ k1;
    uint32_t x0 = 0u + k0, x1 = idx + k1;
#define TF_R(r) { x0 += x1; x1 = rotl32(x1, (r)); x1 ^= x0; }
    TF_R(13) TF_R(15) TF_R(26) TF_R(6)
    x0 += k1; x1 += k2 + 1u;
    TF_R(17) TF_R(29) TF_R(16) TF_R(24)
    x0 += k2; x1 += k0 + 2u;
    TF_R(13) TF_R(15) TF_R(26) TF_R(6)
    x0 += k0; x1 += k1 + 3u;
    TF_R(17) TF_R(29) TF_R(16) TF_R(24)
    x0 += k1; x1 += k2 + 4u;
    TF_R(13) TF_R(15) TF_R(26) TF_R(6)
    x0 += k2; x1 += k0 + 5u;
#undef TF_R
    return x0 ^ x1;
}

// ---------------- convert kernels -------------------------------------------
__global__ void __launch_bounds__(256) split_kernel(
    const float* __restrict__ in, bf16* __restrict__ hi, bf16* __restrict__ lo, int n)
{
    int i = blockIdx.x * 256 + threadIdx.x;
    if (i < n) {
        float v = in[i];
        bf16 h = __float2bfloat16(v);
        hi[i] = h;
        lo[i] = __float2bfloat16(v - __bfloat162float(h));
    }
}

// in [R, C] fp32 -> hi/lo [C, R] bf16
__global__ void __launch_bounds__(256) transpose_split_kernel(
    const float* __restrict__ in, bf16* __restrict__ hi, bf16* __restrict__ lo,
    int R, int C)
{
    __shared__ float t[32][33];
    int tx = threadIdx.x, ty = threadIdx.y;
    int x = blockIdx.x * 32 + tx;
    int y0 = blockIdx.y * 32;
#pragma unroll
    for (int j = 0; j < 4; j++)
        t[ty + 8 * j][tx] = in[(size_t)(y0 + ty + 8 * j) * C + x];
    __syncthreads();
    int ox = y0 + tx;
    int oy0 = blockIdx.x * 32;
#pragma unroll
    for (int j = 0; j < 4; j++) {
        float v = t[tx][ty + 8 * j];
        bf16 h = __float2bfloat16(v);
        size_t o = (size_t)(oy0 + ty + 8 * j) * R + ox;
        hi[o] = h;
        lo[o] = __float2bfloat16(v - __bfloat162float(h));
    }
}

// ---------------- mma.sync split-bf16 GEMM ----------------------------------
// C[M,N] = (Ah+Al)[M,K] @ (Bh+Bl)[N,K]^T  (3 products, fp32 accum)
// CTA 128x128, 8 warps (32m x 64n), BK=16, 3-stage cp.async ring, ONE
// barrier per chunk. 48B smem rows: ldmatrix conflict-free.
// OUT: 0 = fp32 C; 1 = bf16 hi/lo split (Ch, Cl).
static constexpr int ROWB = 48;
static constexpr int OPB  = 128 * ROWB;            // 6144 B per operand tile
static constexpr int STAGE = 4 * OPB;              // Ah,Al,Bh,Bl
static constexpr int GSMEM = 3 * STAGE;            // 73728 B

template <bool CAUSAL_K, bool CAUSAL_SKIP, int OUT>
__global__ void __launch_bounds__(256) gemm_mma_kernel(
    const bf16* __restrict__ Ah, const bf16* __restrict__ Al,
    const bf16* __restrict__ Bh, const bf16* __restrict__ Bl,
    float* __restrict__ C, bf16* __restrict__ Ch, bf16* __restrict__ Cl,
    int M, int N, int K)
{
    if (CAUSAL_SKIP && blockIdx.x > blockIdx.y) return;
    extern __shared__ char smem[];
    const uint32_t sbase = smem_u32(smem);
    const int tid = threadIdx.x;
    const int lane = tid & 31;
    const int wid = tid >> 5;
    const int wm = wid >> 1;
    const int wn = wid & 1;
    const int row0 = blockIdx.y * 128;
    const int col0 = blockIdx.x * 128;
    const int kEnd = CAUSAL_K ? (row0 + 128) : K;
    const int nch = kEnd >> 4;

    const int r = tid >> 1, h = tid & 1;
    const bf16* pAh = Ah + (size_t)(row0 + r) * K + h * 8;
    const bf16* pAl = Al + (size_t)(row0 + r) * K + h * 8;
    const bf16* pBh = Bh + (size_t)(col0 + r) * K + h * 8;
    const bf16* pBl = Bl + (size_t)(col0 + r) * K + h * 8;
    const uint32_t dsto = (uint32_t)(r * ROWB + h * 16);

    float acc[2][8][4];
#pragma unroll
    for (int t = 0; t < 2; t++)
#pragma unroll
        for (int j = 0; j < 8; j++)
#pragma unroll
            for (int q = 0; q < 4; q++) acc[t][j][q] = 0.f;

#define ISSUE(c) do {                                                          \
    int _kc = (c) * 16;                                                        \
    uint32_t _d = sbase + ((c) % 3) * STAGE + dsto;                            \
    cp16(_d + 0 * OPB, pAh + _kc);                                             \
    cp16(_d + 1 * OPB, pAl + _kc);                                             \
    cp16(_d + 2 * OPB, pBh + _kc);                                             \
    cp16(_d + 3 * OPB, pBl + _kc);                                             \
} while (0)

    // prologue: 2 chunks in flight (nch >= 8 always)
    ISSUE(0); CP_COMMIT();
    ISSUE(1); CP_COMMIT();

    const uint32_t a_off = (uint32_t)((wm * 32 + (lane & 15)) * ROWB + (lane >> 4) * 16);
    const uint32_t b_off = (uint32_t)((wn * 64 + (lane & 15)) * ROWB + (lane >> 4) * 16);

    for (int c = 0; c < nch; c++) {
        CP_WAIT1();          // chunk c's group complete (per-thread)
        __syncthreads();     // visible to all; stage c-1 reads all done
        // refill stage (c+2)%3 == (c-1)%3; exactly one commit per iter
        if (c + 2 < nch) ISSUE(c + 2);
        CP_COMMIT();

        const uint32_t st = sbase + (c % 3) * STAGE;
        uint32_t ah[2][4], al[2][4], bh[8][2], bl[8][2];
#pragma unroll
        for (int t = 0; t < 2; t++) {
            LDSM_X4(ah[t][0], ah[t][1], ah[t][2], ah[t][3],
                    st + 0 * OPB + a_off + t * 16 * ROWB);
            LDSM_X4(al[t][0], al[t][1], al[t][2], al[t][3],
                    st + 1 * OPB + a_off + t * 16 * ROWB);
        }
#pragma unroll
        for (int jj = 0; jj < 4; jj++) {
            uint32_t q0, q1, q2, q3;
            LDSM_X4(q0, q1, q2, q3, st + 2 * OPB + b_off + jj * 16 * ROWB);
            bh[2 * jj][0] = q0; bh[2 * jj][1] = q2;
            bh[2 * jj + 1][0] = q1; bh[2 * jj + 1][1] = q3;
            LDSM_X4(q0, q1, q2, q3, st + 3 * OPB + b_off + jj * 16 * ROWB);
            bl[2 * jj][0] = q0; bl[2 * jj][1] = q2;
            bl[2 * jj + 1][0] = q1; bl[2 * jj + 1][1] = q3;
        }
#pragma unroll
        for (int t = 0; t < 2; t++)
#pragma unroll
            for (int j = 0; j < 8; j++) {
                MMA_BF16(acc[t][j], ah[t], bh[j]);
                MMA_BF16(acc[t][j], ah[t], bl[j]);
                MMA_BF16(acc[t][j], al[t], bh[j]);
            }
    }
#undef ISSUE

    // epilogue: frag (t,j): rows wm*32+t*16+{lane>>2, +8}, cols wn*64+j*8+(lane&3)*2
#pragma unroll
    for (int t = 0; t < 2; t++) {
        int r1 = row0 + wm * 32 + t * 16 + (lane >> 2);
#pragma unroll
        for (int j = 0; j < 8; j++) {
            int cc = col0 + wn * 64 + j * 8 + (lane & 3) * 2;
            if (OUT == 0) {
                float2 v0 = {acc[t][j][0], acc[t][j][1]};
                float2 v1 = {acc[t][j][2], acc[t][j][3]};
                *(float2*)(C + (size_t)r1 * N + cc) = v0;
                *(float2*)(C + (size_t)(r1 + 8) * N + cc) = v1;
            } else {
#pragma unroll
                for (int half = 0; half < 2; half++) {
                    float v0 = acc[t][j][2 * half], v1 = acc[t][j][2 * half + 1];
                    bf16 h0 = __float2bfloat16(v0), h1 = __float2bfloat16(v1);
                    __nv_bfloat162 hh, ll;
                    hh.x = h0; hh.y = h1;
                    ll.x = __float2bfloat16(v0 - __bfloat162float(h0));
                    ll.y = __float2bfloat16(v1 - __bfloat162float(h1));
                    size_t o = (size_t)(r1 + 8 * half) * N + cc;
                    *(__nv_bfloat162*)(Ch + o) = hh;
                    *(__nv_bfloat162*)(Cl + o) = ll;
                }
            }
        }
    }
}

// ---------------- softmax + dropout + bf16 split ---------------------------
__global__ void __launch_bounds__(256) softmax_dropout_kernel(
    const float* __restrict__ S, bf16* __restrict__ Ph, bf16* __restrict__ Pl)
{
    __shared__ float buf[SEQ];
    __shared__ float wred[8];
    int i = blockIdx.x;
    int tid = threadIdx.x;
    int lane = tid & 31, wrp = tid >> 5;
    int L = i + 1;
    int rowEnd = ((i >> 7) + 1) << 7;
    const float inv_scale = 0.022097086912079608f;  // 1/sqrt(2048)
    const float* row = S + (size_t)i * SEQ;

    // pass 1: scaled copy to smem + max (vectorized)
    int L4 = L & ~3;
    float lmax = -INFINITY;
    for (int j = tid * 4; j < L4; j += 1024) {
        float4 v = *(const float4*)(row + j);
        v.x *= inv_scale; v.y *= inv_scale; v.z *= inv_scale; v.w *= inv_scale;
        *(float4*)(buf + j) = v;
        lmax = fmaxf(lmax, fmaxf(fmaxf(v.x, v.y), fmaxf(v.z, v.w)));
    }
    for (int j = L4 + tid; j < L; j += 256) {
        float v = row[j] * inv_scale;
        buf[j] = v;
        lmax = fmaxf(lmax, v);
    }
#pragma unroll
    for (int s = 16; s > 0; s >>= 1)
        lmax = fmaxf(lmax, __shfl_xor_sync(0xFFFFFFFFu, lmax, s));
    if (lane == 0) wred[wrp] = lmax;
    __syncthreads();
    float m = fmaxf(fmaxf(fmaxf(wred[0], wred[1]), fmaxf(wred[2], wred[3])),
                    fmaxf(fmaxf(wred[4], wred[5]), fmaxf(wred[6], wred[7])));

    // pass 2: exp + sum
    float lsum = 0.f;
    for (int j = tid; j < L; j += 256) {
        float e = expf(buf[j] - m);
        buf[j] = e;
        lsum += e;
    }
#pragma unroll
    for (int s = 16; s > 0; s >>= 1)
        lsum += __shfl_xor_sync(0xFFFFFFFFu, lsum, s);
    __syncthreads();          // wred reuse
    if (lane == 0) wred[wrp] = lsum;
    __syncthreads();
    float Z = wred[0] + wred[1] + wred[2] + wred[3] +
              wred[4] + wred[5] + wred[6] + wred[7];
    float invZ2 = 2.0f / Z;   // 1/Z * 1/(1-p), p=0.5

    // pass 3: dropout + split, paired bf16x2 stores (rowEnd % 128 == 0)
    uint32_t rowbase = (uint32_t)i * (uint32_t)SEQ;
    for (int j0 = tid * 2; j0 < rowEnd; j0 += 512) {
        float v0 = 0.f, v1 = 0.f;
        if (j0 < L) {
            uint32_t b0 = threefry_bits(rowbase + (uint32_t)j0);
            if (!(b0 & 0x80000000u)) v0 = buf[j0] * invZ2;
        }
        if (j0 + 1 < L) {
            uint32_t b1 = threefry_bits(rowbase + (uint32_t)j0 + 1u);
            if (!(b1 & 0x80000000u)) v1 = buf[j0 + 1] * invZ2;
        }
        bf16 h0 = __float2bfloat16(v0), h1 = __float2bfloat16(v1);
        __nv_bfloat162 hh, ll;
        hh.x = h0; hh.y = h1;
        ll.x = __float2bfloat16(v0 - __bfloat162float(h0));
        ll.y = __float2bfloat16(v1 - __bfloat162float(h1));
        size_t o = (size_t)i * SEQ + j0;
        *(__nv_bfloat162*)(Ph + o) = hh;
        *(__nv_bfloat162*)(Pl + o) = ll;
    }
}

// ---------------------------------------------------------------------------
extern "C" void kernel_launch(void* const* d_in, const int* in_sizes, int n_in,
                              void* d_out, int out_size)
{
    const float* x  = (const float*)d_in[0];
    const float* Wq = (const float*)d_in[1];
    const float* Wk = (const float*)d_in[2];
    const float* Wv = (const float*)d_in[3];
    float* out = (float*)d_out;

    bf16 *xh, *xl, *Wqh, *Wql, *Wkh, *Wkl, *Wvh, *Wvl;
    bf16 *Qh, *Ql, *Kh, *Kl, *VTh, *VTl, *Pph, *Ppl;
    float *V, *S;
    cudaGetSymbolAddress((void**)&xh, g_xh);   cudaGetSymbolAddress((void**)&xl, g_xl);
    cudaGetSymbolAddress((void**)&Wqh, g_Wqh); cudaGetSymbolAddress((void**)&Wql, g_Wql);
    cudaGetSymbolAddress((void**)&Wkh, g_Wkh); cudaGetSymbolAddress((void**)&Wkl, g_Wkl);
    cudaGetSymbolAddress((void**)&Wvh, g_Wvh); cudaGetSymbolAddress((void**)&Wvl, g_Wvl);
    cudaGetSymbolAddress((void**)&V, g_V);     cudaGetSymbolAddress((void**)&S, g_S);
    cudaGetSymbolAddress((void**)&Qh, g_Qh);   cudaGetSymbolAddress((void**)&Ql, g_Ql);
    cudaGetSymbolAddress((void**)&Kh, g_Kh);   cudaGetSymbolAddress((void**)&Kl, g_Kl);
    cudaGetSymbolAddress((void**)&VTh, g_VTh); cudaGetSymbolAddress((void**)&VTl, g_VTl);
    cudaGetSymbolAddress((void**)&Pph, g_Ph);  cudaGetSymbolAddress((void**)&Ppl, g_Pl);

    cudaFuncSetAttribute(gemm_mma_kernel<false, false, 1>,
                         cudaFuncAttributeMaxDynamicSharedMemorySize, GSMEM);
    cudaFuncSetAttribute(gemm_mma_kernel<false, false, 0>,
                         cudaFuncAttributeMaxDynamicSharedMemorySize, GSMEM);
    cudaFuncSetAttribute(gemm_mma_kernel<false, true, 0>,
                         cudaFuncAttributeMaxDynamicSharedMemorySize, GSMEM);
    cudaFuncSetAttribute(gemm_mma_kernel<true, false, 0>,
                         cudaFuncAttributeMaxDynamicSharedMemorySize, GSMEM);

    dim3 blk(256);
    // 1. split x; transpose-split weights
    split_kernel<<<(SEQ * DIN) / 256, blk>>>(x, xh, xl, SEQ * DIN);
    dim3 tblk(32, 8);
    dim3 tgW(DOUT / 32, DIN / 32);
    transpose_split_kernel<<<tgW, tblk>>>(Wq, Wqh, Wql, DIN, DOUT);
    transpose_split_kernel<<<tgW, tblk>>>(Wk, Wkh, Wkl, DIN, DOUT);
    transpose_split_kernel<<<tgW, tblk>>>(Wv, Wvh, Wvl, DIN, DOUT);

    // 2. projections; Q,K write bf16 hi/lo directly from the epilogue
    dim3 gproj(DOUT / 128, SEQ / 128);
    gemm_mma_kernel<false, false, 1><<<gproj, blk, GSMEM>>>(
        xh, xl, Wqh, Wql, nullptr, Qh, Ql, SEQ, DOUT, DIN);
    gemm_mma_kernel<false, false, 1><<<gproj, blk, GSMEM>>>(
        xh, xl, Wkh, Wkl, nullptr, Kh, Kl, SEQ, DOUT, DIN);
    gemm_mma_kernel<false, false, 0><<<gproj, blk, GSMEM>>>(
        xh, xl, Wvh, Wvl, V, nullptr, nullptr, SEQ, DOUT, DIN);

    // 3. transpose-split V
    dim3 tgV(DOUT / 32, SEQ / 32);
    transpose_split_kernel<<<tgV, tblk>>>(V, VTh, VTl, SEQ, DOUT);

    // 4. scores (causal block skip)
    dim3 gsc(SEQ / 128, SEQ / 128);
    gemm_mma_kernel<false, true, 0><<<gsc, blk, GSMEM>>>(
        Qh, Ql, Kh, Kl, S, nullptr, nullptr, SEQ, SEQ, DIN);

    // 5. softmax + dropout + split
    softmax_dropout_kernel<<<SEQ, blk>>>(S, Pph, Ppl);

    // 6. P @ V (k-causal)
    dim3 gpv(DOUT / 128, SEQ / 128);
    gemm_mma_kernel<true, false, 0><<<gpv, blk, GSMEM>>>(
        Pph, Ppl, VTh, VTl, out, nullptr, nullptr, SEQ, DOUT, SEQ);
}